// round 5
// baseline (speedup 1.0000x reference)
#include <cuda_runtime.h>
#include <cstdint>

#define VV 49688
#define DD 128
#define BB 16
#define NN 100

// Per-(node,batch) tag: 0 = not updated, else x-row-index+1.
// Statically zero; consumed entries are cleared to keep the invariant across replays.
__device__ unsigned short g_tag[VV * BB];   // 1.59 MB

__global__ void __launch_bounds__(256) scatter_tags_kernel(
    const int* __restrict__ nodes)
{
    int g = blockIdx.x * blockDim.x + threadIdx.x;
    if (g >= BB * NN) return;
    int b = g / NN;
    int i = g - b * NN;
    int node = __ldg(&nodes[g]);
    g_tag[(size_t)node * BB + b] = (unsigned short)(i + 1);
}

__device__ __forceinline__ void blend_store_row(
    int j, int v, int t, float4 w, uint4 t0, uint4 t1,
    const float* __restrict__ x, const float* __restrict__ alpha,
    float4* __restrict__ out4, int nvec)
{
    float a = __ldg(&alpha[v]);
    float oma = 1.0f - a;
    unsigned words[8] = {t0.x, t0.y, t0.z, t0.w, t1.x, t1.y, t1.z, t1.w};
    size_t base = (size_t)j;
#pragma unroll
    for (int b = 0; b < BB; ++b) {
        unsigned tg = (words[b >> 1] >> ((b & 1) * 16)) & 0xFFFFu;
        float4 r = w;
        if (tg) {
            const float4* xr = (const float4*)(x + (size_t)(tg - 1) * DD);
            float4 xv = __ldg(&xr[t]);
            r.x = oma * w.x + a * xv.x;
            r.y = oma * w.y + a * xv.y;
            r.z = oma * w.z + a * xv.z;
            r.w = oma * w.w + a * xv.w;
        }
        __stcs(&out4[base], r);
        base += (size_t)nvec;
    }
    if (t == 0) {     // all lanes already hold the tags in registers; safe to clear
        uint4 z = make_uint4(0u, 0u, 0u, 0u);
        uint4* tw = (uint4*)&g_tag[(size_t)v * BB];
        tw[0] = z;
        tw[1] = z;
    }
}

// Each thread handles TWO float4s: j0 = h and j1 = h + nvec/2 (two distinct W
// rows per warp-pair). All 6 loads (2x W, 4x tag words) are issued up front so
// per-warp MLP doubles and the stores aren't gated on a single load chain.
// Fast path (both rows untagged, >93% of warps): 32 interleaved broadcast stores.
__global__ void __launch_bounds__(256) fused_copy_blend_kernel(
    const float4* __restrict__ W4,
    const float*  __restrict__ x,
    const float*  __restrict__ alpha,
    float4* __restrict__ out4)
{
    const int nvec = VV * (DD / 4);               // 1,590,016 float4 per copy
    const int HALF = nvec / 2;                    // 795,008
    int h = blockIdx.x * blockDim.x + threadIdx.x;
    if (h >= HALF) return;

    int j0 = h;
    int j1 = h + HALF;
    int v0 = j0 >> 5;
    int v1 = j1 >> 5;
    int t  = h & 31;

    // Issue everything up front: MLP = 6 per thread.
    float4 w0 = __ldg(&W4[j0]);
    float4 w1 = __ldg(&W4[j1]);
    const uint4* tp0 = (const uint4*)&g_tag[(size_t)v0 * BB];
    const uint4* tp1 = (const uint4*)&g_tag[(size_t)v1 * BB];
    uint4 a0 = __ldg(&tp0[0]);
    uint4 a1 = __ldg(&tp0[1]);
    uint4 b0 = __ldg(&tp1[0]);
    uint4 b1 = __ldg(&tp1[1]);

    unsigned any0 = a0.x | a0.y | a0.z | a0.w | a1.x | a1.y | a1.z | a1.w;
    unsigned any1 = b0.x | b0.y | b0.z | b0.w | b1.x | b1.y | b1.z | b1.w;

    if ((any0 | any1) == 0u) {
        size_t p0 = (size_t)j0, p1 = (size_t)j1;
#pragma unroll
        for (int b = 0; b < BB; ++b) {
            __stcs(&out4[p0], w0);
            __stcs(&out4[p1], w1);
            p0 += (size_t)nvec;
            p1 += (size_t)nvec;
        }
    } else {
        if (any0) blend_store_row(j0, v0, t, w0, a0, a1, x, alpha, out4, nvec);
        else {
            size_t p0 = (size_t)j0;
#pragma unroll
            for (int b = 0; b < BB; ++b) { __stcs(&out4[p0], w0); p0 += (size_t)nvec; }
        }
        if (any1) blend_store_row(j1, v1, t, w1, b0, b1, x, alpha, out4, nvec);
        else {
            size_t p1 = (size_t)j1;
#pragma unroll
            for (int b = 0; b < BB; ++b) { __stcs(&out4[p1], w1); p1 += (size_t)nvec; }
        }
    }
}

extern "C" void kernel_launch(void* const* d_in, const int* in_sizes, int n_in,
                              void* d_out, int out_size)
{
    const int*   nodes = (const int*)d_in[0];
    const float* x     = (const float*)d_in[1];
    const float* W     = (const float*)d_in[2];
    const float* alpha = (const float*)d_in[3];
    float*       out   = (float*)d_out;

    scatter_tags_kernel<<<(BB * NN + 255) / 256, 256>>>(nodes);

    const int HALF = VV * (DD / 4) / 2;           // 795,008 threads
    fused_copy_blend_kernel<<<(HALF + 255) / 256, 256>>>(
        (const float4*)W, x, alpha, (float4*)out);
}